// round 11
// baseline (speedup 1.0000x reference)
#include <cuda_runtime.h>
#include <cuda_fp16.h>
#include <cuda_bf16.h>
#include <mma.h>
#include <cstdint>

using namespace nvcuda;

// Problem constants (fixed by the reference)
#define MAXN 50000
#define DIMV 128
#define HEADS 4
#define CH 32
#define MAXE 800000
#define LRELU_SLOPE 0.2f
#define LN_EPS 1e-5f

typedef unsigned long long ull;

// ---------------- scratch (device globals; no allocation allowed) ----------------
// g_hb layout: [N][128] words, word = 2 bf16. word index = layer*64 + pair (pair 0..63).
// => layer-l warp reads contiguous 256B: uint2 at word l*64 + lane*2 (pairs 2lane, 2lane+1
//    = channels 4lane..4lane+3).
__device__ unsigned int g_hb[MAXN * 128];
__device__ float g_srcv[MAXN * 8];          // [node][head][layer]
__device__ float g_dstv[MAXN * 8];          // same layout
__device__ int   g_deg[MAXN];               // edge in-degree (zero-init; self-loop via +1)
__device__ int   g_off[MAXN + 1];           // CSR offsets
__device__ int   g_cursor[MAXN];            // scatter cursors
__device__ int   g_csr[MAXE + MAXN];        // CSR src indices (grouped by dst)
__device__ int   g_bsum[256];               // per-block degree sums

__device__ __forceinline__ float lrelu(float v) { return v > 0.f ? v : LRELU_SLOPE * v; }

__device__ __forceinline__ ull pack2(float x, float y) {
    ull r;
    asm("mov.b64 %0, {%1, %2};" : "=l"(r) : "f"(x), "f"(y));
    return r;
}
__device__ __forceinline__ void unpack2(ull v, float& x, float& y) {
    asm("mov.b64 {%0, %1}, %2;" : "=f"(x), "=f"(y) : "l"(v));
}
__device__ __forceinline__ void ffma2(ull& d, ull a, ull b) {
    asm("fma.rn.f32x2 %0, %1, %2, %0;" : "+l"(d) : "l"(a), "l"(b));
}
__device__ __forceinline__ unsigned int f2bf2(float lo, float hi) {
    unsigned int r;
    asm("cvt.rn.bf16x2.f32 %0, %1, %2;" : "=r"(r) : "f"(hi), "f"(lo));
    return r;
}
// word of two bf16 -> packed f32x2 (exact: bf16->f32 is <<16)
__device__ __forceinline__ ull bf2f2(unsigned int w) {
    ull r;
    asm("mov.b64 %0, {%1, %2};" : "=l"(r) : "r"(w << 16), "r"(w & 0xffff0000u));
    return r;
}

// ---------------- kernel 1: h = x @ [W1|W2] via HMMA + fused attention logits ----------------
// grid: (ceil(n/64), 2 layers), block 256 (8 warps). Tile M=64, N=128, K=128 (2 chunks of 64).
#define XH_LD 72
#define WH_LD 136
#define CS_LD 132
#define GEMM_SMEM 33792   // max(64*72*2 + 64*136*2, 64*132*4)
__global__ __launch_bounds__(256) void gemm_hmma(const float* __restrict__ x,
                                                 const float* __restrict__ W1,
                                                 const float* __restrict__ W2,
                                                 const float* __restrict__ as1,
                                                 const float* __restrict__ ad1,
                                                 const float* __restrict__ as2,
                                                 const float* __restrict__ ad2, int n) {
    __shared__ __align__(16) char buf[GEMM_SMEM];
    half (*Xh)[XH_LD] = (half(*)[XH_LD])buf;                     // 64 x 72 half
    half (*Wh)[WH_LD] = (half(*)[WH_LD])(buf + 64 * XH_LD * 2);  // 64 x 136 half
    float (*Cs)[CS_LD] = (float(*)[CS_LD])buf;                   // 64 x 132 float (aliases)

    int tid = threadIdx.x;
    int rowBase = blockIdx.x * 64;
    int l = blockIdx.y;
    const float* W = (l == 0) ? W1 : W2;
    int warp = tid >> 5;
    int wr = warp & 3;    // 4 row groups of 16
    int wc = warp >> 2;   // 2 col groups of 64

    wmma::fragment<wmma::accumulator, 16, 16, 16, float> acc[4];
#pragma unroll
    for (int j = 0; j < 4; j++) wmma::fill_fragment(acc[j], 0.f);

    int row4 = tid >> 2, q4 = tid & 3;   // 4 threads per row of 64
    for (int k0 = 0; k0 < DIMV; k0 += 64) {
        // load X tile 64x64 (fp32 -> half): 4 threads/row, 16 cols each
        {
            int grow = rowBase + row4;
#pragma unroll
            for (int i = 0; i < 4; i++) {
                float4 v = make_float4(0.f, 0.f, 0.f, 0.f);
                if (grow < n) v = *(const float4*)&x[grow * DIMV + k0 + q4 * 16 + i * 4];
                half2* dst = (half2*)&Xh[row4][q4 * 16 + i * 4];
                dst[0] = __floats2half2_rn(v.x, v.y);
                dst[1] = __floats2half2_rn(v.z, v.w);
            }
        }
        // load W tile 64x128 (fp32 -> half): 4 threads/row, 32 cols each
        {
#pragma unroll
            for (int i = 0; i < 8; i++) {
                float4 v = *(const float4*)&W[(k0 + row4) * DIMV + q4 * 32 + i * 4];
                half2* dst = (half2*)&Wh[row4][q4 * 32 + i * 4];
                dst[0] = __floats2half2_rn(v.x, v.y);
                dst[1] = __floats2half2_rn(v.z, v.w);
            }
        }
        __syncthreads();
#pragma unroll
        for (int kk = 0; kk < 4; kk++) {
            wmma::fragment<wmma::matrix_a, 16, 16, 16, half, wmma::row_major> fa;
            wmma::load_matrix_sync(fa, &Xh[wr * 16][kk * 16], XH_LD);
#pragma unroll
            for (int j = 0; j < 4; j++) {
                wmma::fragment<wmma::matrix_b, 16, 16, 16, half, wmma::row_major> fb;
                wmma::load_matrix_sync(fb, &Wh[kk * 16][wc * 64 + j * 16], WH_LD);
                wmma::mma_sync(acc[j], fa, fb, acc[j]);
            }
        }
        __syncthreads();
    }
    // stage C through smem
#pragma unroll
    for (int j = 0; j < 4; j++)
        wmma::store_matrix_sync(&Cs[wr * 16][wc * 64 + j * 16], acc[j], CS_LD, wmma::mem_row_major);
    __syncthreads();
    {
        int grow = rowBase + row4;
        if (grow < n) {
            // 1) pack 32 channels (pairs q4*16..q4*16+15) to bf16, layer-contiguous layout
#pragma unroll
            for (int g = 0; g < 4; g++) {
                const float* c = &Cs[row4][q4 * 32 + g * 8];
                uint4 pk;
                pk.x = f2bf2(c[0], c[1]);
                pk.y = f2bf2(c[2], c[3]);
                pk.z = f2bf2(c[4], c[5]);
                pk.w = f2bf2(c[6], c[7]);
                *(uint4*)&g_hb[grow * 128 + l * 64 + q4 * 16 + g * 4] = pk;
            }
            // 2) fused attention logits: thread q4 owns head q4 (channels 32q4..32q4+31)
            const float* as = (l == 0) ? as1 : as2;
            const float* ad = (l == 0) ? ad1 : ad2;
            float ps = 0.f, pd = 0.f;
#pragma unroll
            for (int c = 0; c < 32; c += 4) {
                float4 h4 = *(const float4*)&Cs[row4][q4 * 32 + c];
                float4 a4 = *(const float4*)&as[q4 * CH + c];
                float4 d4 = *(const float4*)&ad[q4 * CH + c];
                ps += h4.x * a4.x + h4.y * a4.y + h4.z * a4.z + h4.w * a4.w;
                pd += h4.x * d4.x + h4.y * d4.y + h4.z * d4.z + h4.w * d4.w;
            }
            g_srcv[grow * 8 + q4 * 2 + l] = ps;
            g_dstv[grow * 8 + q4 * 2 + l] = pd;
        }
    }
}

// ---------------- CSR build ----------------
__global__ void count_kernel(const int* __restrict__ ei, int E) {
    int e4 = blockIdx.x * blockDim.x + threadIdx.x;
    int base = e4 * 4;
    if (base + 4 <= E && (E & 3) == 0) {
        int4 d = *(const int4*)&ei[E + base];
        atomicAdd(&g_deg[d.x], 1);
        atomicAdd(&g_deg[d.y], 1);
        atomicAdd(&g_deg[d.z], 1);
        atomicAdd(&g_deg[d.w], 1);
    } else {
        for (int e = base; e < E && e < base + 4; e++) atomicAdd(&g_deg[ei[E + e]], 1);
    }
}

// deg+1 semantics: self-loop included without explicit init.
__global__ __launch_bounds__(256) void scanA_kernel(int n) {
    __shared__ int sm[8];
    int t = threadIdx.x;
    int i = blockIdx.x * 256 + t;
    int v = (i < n) ? g_deg[i] + 1 : 0;
#pragma unroll
    for (int off = 16; off; off >>= 1) v += __shfl_xor_sync(0xffffffffu, v, off);
    if ((t & 31) == 0) sm[t >> 5] = v;
    __syncthreads();
    if (t == 0) {
        int s = 0;
#pragma unroll
        for (int j = 0; j < 8; j++) s += sm[j];
        g_bsum[blockIdx.x] = s;
    }
}

// scanC2: per-block recomputes its exclusive block offset from g_bsum (masked block
// reduction), then does the per-node scan + CSR self-loop placement. Replaces scanB+scanC.
__global__ __launch_bounds__(256) void scanC2_kernel(int nb, int n) {
    __shared__ int rlt[8], rall[8], wsum[8];
    int t = threadIdx.x, lane = t & 31, w = t >> 5;
    int bid = blockIdx.x;
    // phase 1: boff = sum_{j<bid} bsum[j]; tot = sum_all
    int bv = (t < nb) ? g_bsum[t] : 0;
    int blt = (t < bid) ? bv : 0;
    int ball = bv;
#pragma unroll
    for (int off = 16; off; off >>= 1) {
        blt += __shfl_xor_sync(0xffffffffu, blt, off);
        ball += __shfl_xor_sync(0xffffffffu, ball, off);
    }
    if (lane == 0) { rlt[w] = blt; rall[w] = ball; }
    __syncthreads();
    if (t == 0) {
        int a = 0, b = 0;
#pragma unroll
        for (int j = 0; j < 8; j++) { a += rlt[j]; b += rall[j]; }
        rlt[0] = a; rall[0] = b;
    }
    __syncthreads();
    int boff = rlt[0];
    if (bid == 0 && t == 0) g_off[n] = rall[0];
    // phase 2: per-node scan within block
    int i = bid * 256 + t;
    int v = (i < n) ? g_deg[i] + 1 : 0;
    int x = v;
#pragma unroll
    for (int off = 1; off < 32; off <<= 1) {
        int u = __shfl_up_sync(0xffffffffu, x, off);
        if (lane >= off) x += u;
    }
    if (lane == 31) wsum[w] = x;
    __syncthreads();
    if (t == 0) {
        int acc = 0;
#pragma unroll
        for (int j = 0; j < 8; j++) { int tmp = wsum[j]; wsum[j] = acc; acc += tmp; }
    }
    __syncthreads();
    if (i < n) {
        int base = boff + wsum[w] + (x - v);   // exclusive prefix
        g_off[i] = base;
        g_csr[base] = i;          // self-loop first
        g_cursor[i] = base + 1;
        g_deg[i] = 0;             // re-zero for next replay (deterministic)
    }
}

__global__ void scatter_kernel(const int* __restrict__ ei, int E) {
    int e4 = blockIdx.x * blockDim.x + threadIdx.x;
    int base = e4 * 4;
    if (base + 4 <= E && (E & 3) == 0) {
        int4 s = *(const int4*)&ei[base];
        int4 d = *(const int4*)&ei[E + base];
        g_csr[atomicAdd(&g_cursor[d.x], 1)] = s.x;
        g_csr[atomicAdd(&g_cursor[d.y], 1)] = s.y;
        g_csr[atomicAdd(&g_cursor[d.z], 1)] = s.z;
        g_csr[atomicAdd(&g_cursor[d.w], 1)] = s.w;
    } else {
        for (int e = base; e < E && e < base + 4; e++)
            g_csr[atomicAdd(&g_cursor[ei[E + e]], 1)] = ei[e];
    }
}

// ---------------- kernel 3: aggregation (warp per node-layer) + gate + residual + LN ----------------
// block 256 = 8 warps = 4 nodes x 2 layers. grid = ceil(n/4).
__global__ __launch_bounds__(256) void agg_finalize2(
        const float* __restrict__ x,
        const float* __restrict__ b1, const float* __restrict__ b2,
        const float* __restrict__ gW, const float* __restrict__ gb,
        const float* __restrict__ gamma, const float* __restrict__ beta,
        float* __restrict__ out, int n) {
    __shared__ __align__(16) float so[4][2][128];  // 4 KB
    int t = threadIdx.x, lane = t & 31, w = t >> 5;
    int ni = w >> 1, l = w & 1;
    int node = blockIdx.x * 4 + ni;
    int head = lane >> 3;

    if (node < n) {
        float ed = g_dstv[node * 8 + head * 2 + l];
        int beg = g_off[node];
        int end = g_off[node + 1];
        ull na = 0ull, nb_ = 0ull;
        float den = 0.f;
        const unsigned int* hb = &g_hb[l * 64 + lane * 2];
        int p = beg;
        for (; p + 2 <= end; p += 2) {
            int s0 = __ldg(&g_csr[p]);        // uniform address -> L1 broadcast
            int s1 = __ldg(&g_csr[p + 1]);
            uint2 q0 = *(const uint2*)&hb[s0 * 128];
            uint2 q1 = *(const uint2*)&hb[s1 * 128];
            float e0 = __ldg(&g_srcv[s0 * 8 + head * 2 + l]);
            float e1 = __ldg(&g_srcv[s1 * 8 + head * 2 + l]);
            float p0 = __expf(lrelu(e0 + ed));
            float p1 = __expf(lrelu(e1 + ed));
            den += p0 + p1;
            ull pk0 = pack2(p0, p0), pk1 = pack2(p1, p1);
            ffma2(na, pk0, bf2f2(q0.x));
            ffma2(nb_, pk0, bf2f2(q0.y));
            ffma2(na, pk1, bf2f2(q1.x));
            ffma2(nb_, pk1, bf2f2(q1.y));
        }
        if (p < end) {
            int s0 = __ldg(&g_csr[p]);
            uint2 q0 = *(const uint2*)&hb[s0 * 128];
            float e0 = __ldg(&g_srcv[s0 * 8 + head * 2 + l]);
            float p0 = __expf(lrelu(e0 + ed));
            den += p0;
            ull pk0 = pack2(p0, p0);
            ffma2(na, pk0, bf2f2(q0.x));
            ffma2(nb_, pk0, bf2f2(q0.y));
        }
        float inv = 1.f / den;
        float o0, o1f, o2f, o3;
        unpack2(na, o0, o1f);
        unpack2(nb_, o2f, o3);
        const float* bb = l ? b2 : b1;
        float4 b4 = *(const float4*)&bb[lane * 4];
        float4 o;
        o.x = o0 * inv + b4.x;
        o.y = o1f * inv + b4.y;
        o.z = o2f * inv + b4.z;
        o.w = o3 * inv + b4.w;
        *(float4*)&so[ni][l][lane * 4] = o;
    }
    __syncthreads();

    // finalize: warps 0-3, one node each
    if (w < 4) {
        int node2 = blockIdx.x * 4 + w;
        if (node2 < n) {
            int c0 = lane * 4;
            float4 o1 = *(const float4*)&so[w][0][c0];
            float4 o2 = *(const float4*)&so[w][1][c0];
            // gate logits: cat(out1,out2) @ gate_W[256,2]
            float g0 = 0.f, g1 = 0.f;
            {
                const float* w1r = &gW[c0 * 2];
                const float* w2r = &gW[(128 + c0) * 2];
                g0 += o1.x * w1r[0] + o1.y * w1r[2] + o1.z * w1r[4] + o1.w * w1r[6];
                g1 += o1.x * w1r[1] + o1.y * w1r[3] + o1.z * w1r[5] + o1.w * w1r[7];
                g0 += o2.x * w2r[0] + o2.y * w2r[2] + o2.z * w2r[4] + o2.w * w2r[6];
                g1 += o2.x * w2r[1] + o2.y * w2r[3] + o2.z * w2r[5] + o2.w * w2r[7];
            }
#pragma unroll
            for (int off = 16; off; off >>= 1) {
                g0 += __shfl_xor_sync(0xffffffffu, g0, off);
                g1 += __shfl_xor_sync(0xffffffffu, g1, off);
            }
            g0 += gb[0]; g1 += gb[1];
            float mx = fmaxf(g0, g1);
            float e0 = __expf(g0 - mx), e1 = __expf(g1 - mx);
            float inv_se = 1.f / (e0 + e1);
            float w0 = e0 * inv_se, w1 = e1 * inv_se;

            float4 xv = *(const float4*)&x[node2 * DIMV + c0];
            float4 y;
            y.x = xv.x + w0 * o1.x + w1 * o2.x;
            y.y = xv.y + w0 * o1.y + w1 * o2.y;
            y.z = xv.z + w0 * o1.z + w1 * o2.z;
            y.w = xv.w + w0 * o1.w + w1 * o2.w;
            float sum = y.x + y.y + y.z + y.w;
            float sq  = y.x * y.x + y.y * y.y + y.z * y.z + y.w * y.w;
#pragma unroll
            for (int off = 16; off; off >>= 1) {
                sum += __shfl_xor_sync(0xffffffffu, sum, off);
                sq  += __shfl_xor_sync(0xffffffffu, sq, off);
            }
            float mu = sum * (1.f / DIMV);
            float var = sq * (1.f / DIMV) - mu * mu;
            float inv = rsqrtf(var + LN_EPS);
            float4 gm = *(const float4*)&gamma[c0];
            float4 bt = *(const float4*)&beta[c0];
            float4 r;
            r.x = (y.x - mu) * inv * gm.x + bt.x;
            r.y = (y.y - mu) * inv * gm.y + bt.y;
            r.z = (y.z - mu) * inv * gm.z + bt.z;
            r.w = (y.w - mu) * inv * gm.w + bt.w;
            *(float4*)&out[node2 * DIMV + c0] = r;
        }
    }
}

// ---------------- stream/event infrastructure (created once at load) ----------------
static cudaStream_t g_s1;
static cudaEvent_t g_evFork, g_evJoin;
static int g_stream_init = []() {
    cudaStreamCreateWithFlags(&g_s1, cudaStreamNonBlocking);
    cudaEventCreateWithFlags(&g_evFork, cudaEventDisableTiming);
    cudaEventCreateWithFlags(&g_evJoin, cudaEventDisableTiming);
    return 0;
}();

// ---------------- launch ----------------
extern "C" void kernel_launch(void* const* d_in, const int* in_sizes, int n_in,
                              void* d_out, int out_size) {
    const float* x   = (const float*)d_in[0];
    const int*   ei  = (const int*)d_in[1];
    const float* W1  = (const float*)d_in[2];
    const float* b1  = (const float*)d_in[3];
    const float* as1 = (const float*)d_in[4];
    const float* ad1 = (const float*)d_in[5];
    const float* W2  = (const float*)d_in[6];
    const float* b2  = (const float*)d_in[7];
    const float* as2 = (const float*)d_in[8];
    const float* ad2 = (const float*)d_in[9];
    const float* gW  = (const float*)d_in[10];
    const float* gb  = (const float*)d_in[11];
    const float* gam = (const float*)d_in[12];
    const float* bet = (const float*)d_in[13];
    float* out = (float*)d_out;

    int n = in_sizes[0] / DIMV;       // nodes
    int E = in_sizes[1] / 2;          // edges (before self-loops)
    int nb = (n + 255) / 256;         // scan blocks (<= 256)
    int e4 = (E + 3) / 4;             // 4-edge work items

    // Fork: CSR build (depends only on ei) on side stream
    cudaEventRecord(g_evFork, 0);
    cudaStreamWaitEvent(g_s1, g_evFork, 0);

    // Branch A (stream 0): h = x @ [W1|W2] via HMMA + fused logits
    gemm_hmma<<<dim3((n + 63) / 64, 2), 256>>>(x, W1, W2, as1, ad1, as2, ad2, n);

    // Branch B (stream s1): CSR build (dst-grouped)
    count_kernel<<<(e4 + 255) / 256, 256, 0, g_s1>>>(ei, E);
    scanA_kernel<<<nb, 256, 0, g_s1>>>(n);
    scanC2_kernel<<<nb, 256, 0, g_s1>>>(nb, n);
    scatter_kernel<<<(e4 + 255) / 256, 256, 0, g_s1>>>(ei, E);

    // Join
    cudaEventRecord(g_evJoin, g_s1);
    cudaStreamWaitEvent(0, g_evJoin, 0);

    // Aggregation + gate + residual + LN (warp per node-layer)
    agg_finalize2<<<(n + 3) / 4, 256>>>(x, b1, b2, gW, gb, gam, bet, out, n);
}